// round 11
// baseline (speedup 1.0000x reference)
#include <cuda_runtime.h>
#include <cuda_fp16.h>
#include <cstdint>

// ---------------------------------------------------------------------------
// Problem constants
// ---------------------------------------------------------------------------
#define OUT_N    8192
#define IN_K     8192
#define BATCH    64
#define TILE_N   128                  // W rows per CTA
#define KSPLIT   8
#define NGRPS    (OUT_N / TILE_N)     // 64
#define NSUB     32                   // k32 subchunks per CTA (k total 1024)
#define NTHREADS 256

// SMEM: 64B rows (4 x 16B units), XOR-swizzled -> no padding needed.
// W stage: 128 rows x 64 B = 8192.  x stage: 64 rows x 64 B = 4096.
#define W_BYTES  8192
#define X_BYTES  4096

// swizzle: 16B-unit column kv (0..3) XOR'd with (row>>1)&3.
// ldsm reads 8 consecutive rows at fixed kv -> banks (4r + kv^((r>>1)&3)) mod 8
// hit all 8 16B bank-groups (proof: {kv..kv^3} U {+4 images}). STS.128
// quarter-warp phases (4 rows x 2 kv) also land on 8 distinct groups.
#define SWZ(row, kv) ((kv) ^ (((row) >> 1) & 3))

// Static scratch: x converted to fp16 (1 MiB)
__device__ __half g_xh[BATCH * IN_K];

// ---------------------------------------------------------------------------
// PTX helpers (family-portable: ptxas target is sm_103, no tcgen05)
// ---------------------------------------------------------------------------
__device__ __forceinline__ void ldsm_x4(uint32_t& r0, uint32_t& r1, uint32_t& r2,
                                        uint32_t& r3, uint32_t addr) {
    asm volatile("ldmatrix.sync.aligned.m8n8.x4.shared.b16 {%0,%1,%2,%3}, [%4];"
                 : "=r"(r0), "=r"(r1), "=r"(r2), "=r"(r3) : "r"(addr));
}
__device__ __forceinline__ void mma_16816(float* c, uint32_t a0, uint32_t a1,
                                          uint32_t a2, uint32_t a3,
                                          uint32_t b0, uint32_t b1) {
    asm volatile(
        "mma.sync.aligned.m16n8k16.row.col.f32.f16.f16.f32 "
        "{%0,%1,%2,%3},{%4,%5,%6,%7},{%8,%9},{%0,%1,%2,%3};"
        : "+f"(c[0]), "+f"(c[1]), "+f"(c[2]), "+f"(c[3])
        : "r"(a0), "r"(a1), "r"(a2), "r"(a3), "r"(b0), "r"(b1));
}
__device__ __forceinline__ void cp_async16(uint32_t dst, const void* src) {
    asm volatile("cp.async.cg.shared.global [%0], [%1], 16;"
                 :: "r"(dst), "l"(src) : "memory");
}
__device__ __forceinline__ void cp_commit() {
    asm volatile("cp.async.commit_group;" ::: "memory");
}

// ---------------------------------------------------------------------------
// Kernel 1: convert x fp32->fp16 AND zero-init out (both 131072 float4 units)
// ---------------------------------------------------------------------------
__global__ __launch_bounds__(256) void prep_kernel(const float* __restrict__ x,
                                                   float* __restrict__ out) {
    int i = blockIdx.x * 256 + threadIdx.x;
    float4 v = reinterpret_cast<const float4*>(x)[i];
    __half2 h01 = __floats2half2_rn(v.x, v.y);
    __half2 h23 = __floats2half2_rn(v.z, v.w);
    uint2 o;
    o.x = *reinterpret_cast<uint32_t*>(&h01);
    o.y = *reinterpret_cast<uint32_t*>(&h23);
    reinterpret_cast<uint2*>(g_xh)[i] = o;
    reinterpret_cast<float4*>(out)[i] = make_float4(0.f, 0.f, 0.f, 0.f);
}

// ---------------------------------------------------------------------------
// Kernel 2: int4-dequant GEMM (mma.sync), k32 subchunk pipeline, 4 CTAs/SM.
// Grid = 512 CTAs: bid & 63 = n-group (128 W rows), bid >> 6 = k-group.
// Warp layout 2(m) x 4(n): warp owns 32 batch rows x 32 output cols.
// Scales live in 4 half2 registers/thread (dequant row fixed = tid>>1).
// Phase shift (R9/R10 scheme): iter sub stages subchunk sub+1 before MMA(sub).
// ---------------------------------------------------------------------------
__global__ __launch_bounds__(NTHREADS, 4)
void dq_gemm_kernel(const int*   __restrict__ packed,
                    const float* __restrict__ scales,
                    float*       __restrict__ out)
{
    __shared__ __align__(16) char sWm[2 * W_BYTES];   // W dequant stages
    __shared__ __align__(16) char sXm[2 * X_BYTES];   // x stages

    const uint32_t wb0 = (uint32_t)__cvta_generic_to_shared(sWm);
    const uint32_t xb0 = (uint32_t)__cvta_generic_to_shared(sXm);

    const int tid  = threadIdx.x;
    const int wid  = tid >> 5;
    const int lane = tid & 31;
    const int mh   = wid & 1;          // batch half
    const int ng   = wid >> 1;         // 32-col group
    const int n0   = (blockIdx.x & 63) * TILE_N;
    const int kg   = blockIdx.x >> 6;  // 0..7
    const int ks0  = kg * NSUB;        // global k32-subchunk base

    float acc[2][4][4];
    #pragma unroll
    for (int m = 0; m < 2; m++)
        #pragma unroll
        for (int n = 0; n < 4; n++)
            #pragma unroll
            for (int j = 0; j < 4; j++) acc[m][n][j] = 0.f;

    const uint4* pk4 = reinterpret_cast<const uint4*>(packed); // row = 1024 uint4
    const uint32_t c1032b = 0x64086408u;                       // half2(1032,1032)
    const __half2 c1032 = *reinterpret_cast<const __half2*>(&c1032b);

    // ---- per-thread scales: dequant row = tid>>1, 8 chunks -> 4 half2 ----
    const int drow = tid >> 1;                       // 0..127
    const int dcol = tid & 1;                        // 16B-unit pair selector
    __half2 hs[4];
    {
        const float4* sp = reinterpret_cast<const float4*>(
            scales + (size_t)(n0 + drow) * 64 + kg * 8);
        float4 f0 = sp[0], f1 = sp[1];
        hs[0] = __floats2half2_rn(f0.x, f0.y);
        hs[1] = __floats2half2_rn(f0.z, f0.w);
        hs[2] = __floats2half2_rn(f1.x, f1.y);
        hs[3] = __floats2half2_rn(f1.z, f1.w);
    }

    // ---- packed-W prefetch: one k32 sub = 512 uint4 = 2/thread ------------
    uint4 pv[2];
    auto prefetch = [&](int ks) {
        #pragma unroll
        for (int q = 0; q < 2; q++)
            pv[q] = pk4[(size_t)(n0 + drow) * 1024 + ks * 4 + dcol * 2 + q];
    };

    // ---- x tile cp.async (256 x 16B units = 1/thread) ---------------------
    auto stage_x = [&](int ks, int s) {
        const uint32_t xb = xb0 + s * X_BYTES;
        int b = tid >> 2, kv = tid & 3;
        cp_async16(xb + b * 64 + SWZ(b, kv) * 16,
                   &g_xh[(size_t)b * IN_K + ks * 32 + kv * 8]);
        cp_commit();
    };

    // dequant pv (subchunk sub) -> W buffer s (2 x STS.128 / thread)
    auto dequant_sts = [&](int s, int sub) {
        const uint32_t stage = wb0 + s * W_BYTES;
        const int lch = sub >> 2;                    // k128 scale chunk
        __half2 hp = hs[lch >> 1];
        __half2 s2 = (lch & 1) ? __high2half2(hp) : __low2half2(hp);
        #pragma unroll
        for (int q = 0; q < 2; q++) {
            int kv = dcol * 2 + q;
            uint32_t w[4] = { pv[q].x, pv[q].y, pv[q].z, pv[q].w };
            uint32_t o[4];
            #pragma unroll
            for (int j = 0; j < 4; j++) {
                uint32_t t = ((w[j] * 0x1001u) & 0x000F000Fu) | 0x64006400u;
                __half2 hv = __hmul2(__hsub2(*reinterpret_cast<__half2*>(&t), c1032), s2);
                o[j] = *reinterpret_cast<uint32_t*>(&hv);
            }
            asm volatile("st.shared.v4.b32 [%0], {%1,%2,%3,%4};"
                         :: "r"(stage + drow * 64 + SWZ(drow, kv) * 16),
                            "r"(o[0]), "r"(o[1]), "r"(o[2]), "r"(o[3]) : "memory");
        }
    };

    // ---- prologue ---------------------------------------------------------
    prefetch(ks0);           // pv = packed[sub 0]
    stage_x(ks0, 0);         // x[0] in flight
    dequant_sts(0, 0);       // W[0] STS -> stage 0
    prefetch(ks0 + 1);       // pv = packed[sub 1]

    // Invariant at iteration entry (sub, s = sub&1):
    //   x[sub] cp.async group pending; W[sub] STS issued into stage s;
    //   pv = packed[sub+1].
    for (int sub = 0; sub < NSUB; sub++) {
        const int s = sub & 1;

        asm volatile("cp.async.wait_group 0;" ::: "memory");  // x[sub] landed
        __syncthreads();     // W[sub]/x[sub] visible; stage s^1 free

        if (sub + 1 < NSUB) {
            stage_x(ks0 + sub + 1, s ^ 1);       // x[sub+1] in flight
            dequant_sts(s ^ 1, sub + 1);         // W[sub+1] STS (other buffer)
            if (sub + 2 < NSUB) prefetch(ks0 + sub + 2);  // LDGs overlap MMA
        }

        // ---- MMA(sub): 2 k16 tiles, warp tile 32(m) x 32(n), stage s ------
        const uint32_t wbase = wb0 + s * W_BYTES;
        const uint32_t xbase = xb0 + s * X_BYTES;
        #pragma unroll
        for (int kt = 0; kt < 2; kt++) {
            uint32_t b[4][2];             // [nt][b0,b1]
            #pragma unroll
            for (int np = 0; np < 2; np++) {
                int br = ng * 32 + np * 16 + ((lane >> 4) & 1) * 8 + (lane & 7);
                int kvB = kt * 2 + ((lane >> 3) & 1);
                ldsm_x4(b[np*2][0], b[np*2][1], b[np*2+1][0], b[np*2+1][1],
                        wbase + (uint32_t)(br * 64 + SWZ(br, kvB) * 16));
            }
            #pragma unroll
            for (int mt = 0; mt < 2; mt++) {
                uint32_t a0, a1, a2, a3;
                int ar = mh * 32 + mt * 16 + (lane & 15);
                int kvA = kt * 2 + (lane >> 4);
                ldsm_x4(a0, a1, a2, a3,
                        xbase + (uint32_t)(ar * 64 + SWZ(ar, kvA) * 16));
                #pragma unroll
                for (int nt = 0; nt < 4; nt++)
                    mma_16816(acc[mt][nt], a0, a1, a2, a3, b[nt][0], b[nt][1]);
            }
        }
    }

    // ---- epilogue: vectorized float2 atomics (k-split merge) --------------
    #pragma unroll
    for (int mt = 0; mt < 2; mt++) {
        #pragma unroll
        for (int nt = 0; nt < 4; nt++) {
            int m = mh * 32 + mt * 16 + (lane >> 2);
            int n = n0 + ng * 32 + nt * 8 + (lane & 3) * 2;
            atomicAdd(reinterpret_cast<float2*>(&out[(size_t)m * OUT_N + n]),
                      make_float2(acc[mt][nt][0], acc[mt][nt][1]));
            atomicAdd(reinterpret_cast<float2*>(&out[(size_t)(m + 8) * OUT_N + n]),
                      make_float2(acc[mt][nt][2], acc[mt][nt][3]));
        }
    }
}

// ---------------------------------------------------------------------------
extern "C" void kernel_launch(void* const* d_in, const int* in_sizes, int n_in,
                              void* d_out, int out_size) {
    const float* x      = (const float*)d_in[0];
    const int*   packed = (const int*)d_in[1];
    const float* scales = (const float*)d_in[2];
    float*       out    = (float*)d_out;

    prep_kernel<<<512, 256>>>(x, out);
    dq_gemm_kernel<<<NGRPS * KSPLIT, NTHREADS>>>(packed, scales, out);
}

// round 12
// speedup vs baseline: 1.1084x; 1.1084x over previous
#include <cuda_runtime.h>
#include <cuda_fp16.h>
#include <cstdint>

// ---------------------------------------------------------------------------
// Problem constants
// ---------------------------------------------------------------------------
#define OUT_N    8192
#define IN_K     8192
#define BATCH    64
#define TILE_N   128                  // W rows per CTA
#define KSPLIT   16
#define NGRPS    (OUT_N / TILE_N)     // 64
#define NSUB     8                    // k64 subchunks per CTA (k total 512)
#define NTHREADS 256

// SMEM layout (bytes). Rows hold 64 halfs = 128 B, padded stride 144 B
// (odd multiple of 16 B -> conflict-free ldmatrix over 8-row groups)
#define RS          144
#define W_BYTES     (TILE_N * RS)          // 18432
#define X_OFF       W_BYTES
#define X_BYTES     (BATCH * RS)           // 9216
#define STAGE_BYTES (W_BYTES + X_BYTES)    // 27648
#define SMEM_TOTAL  (2 * STAGE_BYTES)      // 55296 -> 3 CTAs/SM

// Static scratch: x converted to fp16 (1 MiB)
__device__ __half g_xh[BATCH * IN_K];

// ---------------------------------------------------------------------------
// PTX helpers (family-portable: ptxas target is sm_103, no tcgen05)
// ---------------------------------------------------------------------------
__device__ __forceinline__ void ldsm_x4(uint32_t& r0, uint32_t& r1, uint32_t& r2,
                                        uint32_t& r3, uint32_t addr) {
    asm volatile("ldmatrix.sync.aligned.m8n8.x4.shared.b16 {%0,%1,%2,%3}, [%4];"
                 : "=r"(r0), "=r"(r1), "=r"(r2), "=r"(r3) : "r"(addr));
}
__device__ __forceinline__ void mma_16816(float* c, uint32_t a0, uint32_t a1,
                                          uint32_t a2, uint32_t a3,
                                          uint32_t b0, uint32_t b1) {
    asm volatile(
        "mma.sync.aligned.m16n8k16.row.col.f32.f16.f16.f32 "
        "{%0,%1,%2,%3},{%4,%5,%6,%7},{%8,%9},{%0,%1,%2,%3};"
        : "+f"(c[0]), "+f"(c[1]), "+f"(c[2]), "+f"(c[3])
        : "r"(a0), "r"(a1), "r"(a2), "r"(a3), "r"(b0), "r"(b1));
}
__device__ __forceinline__ void cp_async16(uint32_t dst, const void* src) {
    asm volatile("cp.async.cg.shared.global [%0], [%1], 16;"
                 :: "r"(dst), "l"(src) : "memory");
}
__device__ __forceinline__ void cp_commit() {
    asm volatile("cp.async.commit_group;" ::: "memory");
}

// ---------------------------------------------------------------------------
// Kernel 1: convert x fp32->fp16 AND zero-init out. 4 independent float4 per
// thread (MLP=4) so DRAM latency overlaps. 128 blocks x 256 thr x 4 = 131072.
// ---------------------------------------------------------------------------
__global__ __launch_bounds__(256) void prep_kernel(const float* __restrict__ x,
                                                   float* __restrict__ out) {
    int base = blockIdx.x * 256 + threadIdx.x;
    #pragma unroll
    for (int k = 0; k < 4; k++) {
        int i = base + k * 32768;
        float4 v = reinterpret_cast<const float4*>(x)[i];
        __half2 h01 = __floats2half2_rn(v.x, v.y);
        __half2 h23 = __floats2half2_rn(v.z, v.w);
        uint2 o;
        o.x = *reinterpret_cast<uint32_t*>(&h01);
        o.y = *reinterpret_cast<uint32_t*>(&h23);
        reinterpret_cast<uint2*>(g_xh)[i] = o;
        reinterpret_cast<float4*>(out)[i] = make_float4(0.f, 0.f, 0.f, 0.f);
    }
}

// ---------------------------------------------------------------------------
// Kernel 2: int4-dequant GEMM (mma.sync), k64 subchunk pipeline, 3 CTAs/SM.
// Grid = 1024 CTAs: bid & 63 = n-group (128 W rows), bid >> 6 = k-group (k512).
// Warp layout 2(m) x 4(n): warp owns 32 batch rows x 32 output cols.
// Dequant thread owns one W row (tid>>1); its 4 scales live in 2 half2 regs.
// Phase shift (R9/R10 scheme): iter sub stages subchunk sub+1 before MMA(sub).
// ---------------------------------------------------------------------------
__global__ __launch_bounds__(NTHREADS, 3)
void dq_gemm_kernel(const int*   __restrict__ packed,
                    const float* __restrict__ scales,
                    float*       __restrict__ out)
{
    extern __shared__ __align__(16) char dsm[];
    const uint32_t sb = (uint32_t)__cvta_generic_to_shared(dsm);

    const int tid  = threadIdx.x;
    const int wid  = tid >> 5;
    const int lane = tid & 31;
    const int mh   = wid & 1;          // batch half
    const int ng   = wid >> 1;         // 32-col group
    const int n0   = (blockIdx.x & 63) * TILE_N;
    const int kg   = blockIdx.x >> 6;  // 0..15
    const int ks0  = kg * NSUB;        // global k64-subchunk base

    float acc[2][4][4];
    #pragma unroll
    for (int m = 0; m < 2; m++)
        #pragma unroll
        for (int n = 0; n < 4; n++)
            #pragma unroll
            for (int j = 0; j < 4; j++) acc[m][n][j] = 0.f;

    const uint4* pk4 = reinterpret_cast<const uint4*>(packed); // row = 1024 uint4
    const uint32_t c1032b = 0x64086408u;                       // half2(1032,1032)
    const __half2 c1032 = *reinterpret_cast<const __half2*>(&c1032b);

    // ---- per-thread dequant mapping: one W row, 8 of its 16B k-units ------
    const int drow = tid >> 1;                    // 0..127
    const int da   = tid & 1;                     // which half of the 8 units
    const int krot = (drow >> 3) & 7;             // de-collides r vs r+8 banks

    // ---- register scales: 4 k128 chunks for this row -> 2 half2 -----------
    __half2 hs[2];
    {
        float4 f = *reinterpret_cast<const float4*>(
            scales + (size_t)(n0 + drow) * 64 + kg * 4);
        hs[0] = __floats2half2_rn(f.x, f.y);
        hs[1] = __floats2half2_rn(f.z, f.w);
    }

    // ---- packed-W prefetch: one k64 sub = 1024 uint4 = 4/thread -----------
    // unit kv(j) = (da*4 + j + krot) & 7  (matches STS placement below)
    uint4 pv[4];
    auto prefetch = [&](int ks) {
        #pragma unroll
        for (int j = 0; j < 4; j++) {
            int kv = (da * 4 + j + krot) & 7;
            pv[j] = pk4[(size_t)(n0 + drow) * 1024 + ks * 8 + kv];
        }
    };

    // ---- x tile cp.async (512 x 16B units = 2/thread) ---------------------
    auto stage_x = [&](int ks, int s) {
        const uint32_t xb = sb + s * STAGE_BYTES + X_OFF;
        #pragma unroll
        for (int j = 0; j < 2; j++) {
            int u = tid + (j << 8);               // 0..511
            int b = u >> 3, kv = u & 7;
            cp_async16(xb + b * RS + kv * 16,
                       &g_xh[(size_t)b * IN_K + ks * 64 + kv * 8]);
        }
        cp_commit();
    };

    // dequant pv (subchunk sub) -> W buffer s (4 x STS.128 / thread)
    auto dequant_sts = [&](int s, int sub) {
        const uint32_t stage = sb + s * STAGE_BYTES;
        const int lch = sub >> 1;                 // k128 scale chunk 0..3
        __half2 hp = hs[lch >> 1];
        __half2 s2 = (lch & 1) ? __high2half2(hp) : __low2half2(hp);
        #pragma unroll
        for (int j = 0; j < 4; j++) {
            int kv = (da * 4 + j + krot) & 7;
            uint32_t w[4] = { pv[j].x, pv[j].y, pv[j].z, pv[j].w };
            uint32_t o[4];
            #pragma unroll
            for (int q = 0; q < 4; q++) {
                uint32_t t = ((w[q] * 0x1001u) & 0x000F000Fu) | 0x64006400u;
                __half2 hv = __hmul2(__hsub2(*reinterpret_cast<__half2*>(&t), c1032), s2);
                o[q] = *reinterpret_cast<uint32_t*>(&hv);
            }
            asm volatile("st.shared.v4.b32 [%0], {%1,%2,%3,%4};"
                         :: "r"(stage + drow * RS + kv * 16),
                            "r"(o[0]), "r"(o[1]), "r"(o[2]), "r"(o[3]) : "memory");
        }
    };

    // ---- prologue ---------------------------------------------------------
    prefetch(ks0);           // pv = packed[sub 0]
    stage_x(ks0, 0);         // x[0] in flight
    dequant_sts(0, 0);       // W[0] STS -> stage 0
    prefetch(ks0 + 1);       // pv = packed[sub 1]

    // Invariant at iteration entry (sub, s = sub&1):
    //   x[sub] cp.async group pending; W[sub] STS issued into stage s;
    //   pv = packed[sub+1].
    for (int sub = 0; sub < NSUB; sub++) {
        const int s = sub & 1;

        asm volatile("cp.async.wait_group 0;" ::: "memory");  // x[sub] landed
        __syncthreads();     // W[sub]/x[sub] visible; stage s^1 free

        if (sub + 1 < NSUB) {
            stage_x(ks0 + sub + 1, s ^ 1);       // x[sub+1] in flight
            dequant_sts(s ^ 1, sub + 1);         // W[sub+1] STS (other buffer)
            if (sub + 2 < NSUB) prefetch(ks0 + sub + 2);  // LDGs overlap MMA
        }

        // ---- MMA(sub): 4 k16 tiles, warp tile 32(m) x 32(n), stage s ------
        const uint32_t wbase = sb + s * STAGE_BYTES;
        const uint32_t xbase = wbase + X_OFF;
        #pragma unroll
        for (int kt = 0; kt < 4; kt++) {
            uint32_t b[4][2];             // [nt][b0,b1]
            #pragma unroll
            for (int np = 0; np < 2; np++) {
                int br = ng * 32 + np * 16 + ((lane >> 4) & 1) * 8 + (lane & 7);
                int bc = kt * 16 + ((lane >> 3) & 1) * 8;
                ldsm_x4(b[np*2][0], b[np*2][1], b[np*2+1][0], b[np*2+1][1],
                        wbase + (uint32_t)(br * RS + bc * 2));
            }
            #pragma unroll
            for (int mt = 0; mt < 2; mt++) {
                uint32_t a0, a1, a2, a3;
                int ar = mh * 32 + mt * 16 + (lane & 15);
                int ac = kt * 16 + (lane >> 4) * 8;
                ldsm_x4(a0, a1, a2, a3, xbase + (uint32_t)(ar * RS + ac * 2));
                #pragma unroll
                for (int nt = 0; nt < 4; nt++)
                    mma_16816(acc[mt][nt], a0, a1, a2, a3, b[nt][0], b[nt][1]);
            }
        }
    }

    // ---- epilogue: vectorized float2 atomics (k-split merge) --------------
    #pragma unroll
    for (int mt = 0; mt < 2; mt++) {
        #pragma unroll
        for (int nt = 0; nt < 4; nt++) {
            int m = mh * 32 + mt * 16 + (lane >> 2);
            int n = n0 + ng * 32 + nt * 8 + (lane & 3) * 2;
            atomicAdd(reinterpret_cast<float2*>(&out[(size_t)m * OUT_N + n]),
                      make_float2(acc[mt][nt][0], acc[mt][nt][1]));
            atomicAdd(reinterpret_cast<float2*>(&out[(size_t)(m + 8) * OUT_N + n]),
                      make_float2(acc[mt][nt][2], acc[mt][nt][3]));
        }
    }
}

// ---------------------------------------------------------------------------
extern "C" void kernel_launch(void* const* d_in, const int* in_sizes, int n_in,
                              void* d_out, int out_size) {
    const float* x      = (const float*)d_in[0];
    const int*   packed = (const int*)d_in[1];
    const float* scales = (const float*)d_in[2];
    float*       out    = (float*)d_out;

    cudaFuncSetAttribute(dq_gemm_kernel,
                         cudaFuncAttributeMaxDynamicSharedMemorySize, SMEM_TOTAL);

    prep_kernel<<<128, 256>>>(x, out);
    dq_gemm_kernel<<<NGRPS * KSPLIT, NTHREADS, SMEM_TOTAL>>>(packed, scales, out);
}

// round 13
// speedup vs baseline: 1.1969x; 1.0799x over previous
#include <cuda_runtime.h>
#include <cuda_fp16.h>
#include <cstdint>

// ---------------------------------------------------------------------------
// Problem constants  (R10 champion configuration)
// ---------------------------------------------------------------------------
#define OUT_N    8192
#define IN_K     8192
#define BATCH    64
#define TILE_N   128                  // W rows per CTA
#define KSPLIT   8
#define NGRPS    (OUT_N / TILE_N)     // 64
#define NSUB     16                   // k64 subchunks per CTA (k total 1024)
#define NCH      8                    // k128 scale-chunks per CTA
#define NTHREADS 256

// SMEM layout (bytes). Rows hold 64 halfs = 128 B, padded stride 144 B
// (odd multiple of 16 B -> conflict-free ldmatrix over 8-row groups)
#define RS          144
#define W_BYTES     (TILE_N * RS)          // 18432
#define X_OFF       W_BYTES
#define X_BYTES     (BATCH * RS)           // 9216
#define STAGE_BYTES (W_BYTES + X_BYTES)    // 27648
#define SCALE_OFF   (2 * STAGE_BYTES)      // 55296
#define SCALE_BYTES (NCH * TILE_N * 4)     // 4096
#define SMEM_TOTAL  (SCALE_OFF + SCALE_BYTES)  // 59392 -> 3 CTAs/SM

// Static scratch: x converted to fp16 (1 MiB)
__device__ __half g_xh[BATCH * IN_K];

// ---------------------------------------------------------------------------
// PTX helpers (family-portable: ptxas target is sm_103, no tcgen05)
// ---------------------------------------------------------------------------
__device__ __forceinline__ void ldsm_x4(uint32_t& r0, uint32_t& r1, uint32_t& r2,
                                        uint32_t& r3, uint32_t addr) {
    asm volatile("ldmatrix.sync.aligned.m8n8.x4.shared.b16 {%0,%1,%2,%3}, [%4];"
                 : "=r"(r0), "=r"(r1), "=r"(r2), "=r"(r3) : "r"(addr));
}
__device__ __forceinline__ void mma_16816(float* c, uint32_t a0, uint32_t a1,
                                          uint32_t a2, uint32_t a3,
                                          uint32_t b0, uint32_t b1) {
    asm volatile(
        "mma.sync.aligned.m16n8k16.row.col.f32.f16.f16.f32 "
        "{%0,%1,%2,%3},{%4,%5,%6,%7},{%8,%9},{%0,%1,%2,%3};"
        : "+f"(c[0]), "+f"(c[1]), "+f"(c[2]), "+f"(c[3])
        : "r"(a0), "r"(a1), "r"(a2), "r"(a3), "r"(b0), "r"(b1));
}
// .ca: co-resident CTAs (same k-group) re-read identical x windows -> L1 hits
__device__ __forceinline__ void cp_async16_ca(uint32_t dst, const void* src) {
    asm volatile("cp.async.ca.shared.global [%0], [%1], 16;"
                 :: "r"(dst), "l"(src) : "memory");
}
__device__ __forceinline__ void cp_commit() {
    asm volatile("cp.async.commit_group;" ::: "memory");
}

// ---------------------------------------------------------------------------
// Kernel 1: convert x fp32->fp16 AND zero-init out. 4 independent float4 per
// thread (MLP=4) so DRAM latency overlaps. 128 blocks x 256 thr x 4 = 131072.
// ---------------------------------------------------------------------------
__global__ __launch_bounds__(256) void prep_kernel(const float* __restrict__ x,
                                                   float* __restrict__ out) {
    int base = blockIdx.x * 256 + threadIdx.x;
    #pragma unroll
    for (int k = 0; k < 4; k++) {
        int i = base + k * 32768;
        float4 v = reinterpret_cast<const float4*>(x)[i];
        __half2 h01 = __floats2half2_rn(v.x, v.y);
        __half2 h23 = __floats2half2_rn(v.z, v.w);
        uint2 o;
        o.x = *reinterpret_cast<uint32_t*>(&h01);
        o.y = *reinterpret_cast<uint32_t*>(&h23);
        reinterpret_cast<uint2*>(g_xh)[i] = o;
        reinterpret_cast<float4*>(out)[i] = make_float4(0.f, 0.f, 0.f, 0.f);
    }
}

// ---------------------------------------------------------------------------
// Kernel 2: int4-dequant GEMM (mma.sync), k64 subchunk pipeline, 3 CTAs/SM.
// Grid = 512 CTAs: bid & 63 = n-group (128 W rows), bid >> 6 = k-group.
// Warp layout 2(m) x 4(n): warp owns 32 batch rows x 32 output cols.
// Phase shift (R9/R10 scheme): iter sub stages subchunk sub+1 before MMA(sub).
// ---------------------------------------------------------------------------
__global__ __launch_bounds__(NTHREADS, 3)
void dq_gemm_kernel(const int*   __restrict__ packed,
                    const float* __restrict__ scales,
                    float*       __restrict__ out)
{
    extern __shared__ __align__(16) char dsm[];
    const uint32_t sb = (uint32_t)__cvta_generic_to_shared(dsm);
    float* sScale = reinterpret_cast<float*>(dsm + SCALE_OFF);

    const int tid  = threadIdx.x;
    const int wid  = tid >> 5;
    const int lane = tid & 31;
    const int mh   = wid & 1;          // batch half
    const int ng   = wid >> 1;         // 32-col group
    const int n0   = (blockIdx.x & 63) * TILE_N;
    const int kg   = blockIdx.x >> 6;  // 0..7
    const int ks0  = kg * NSUB;        // global k64-subchunk base

    float acc[2][4][4];
    #pragma unroll
    for (int m = 0; m < 2; m++)
        #pragma unroll
        for (int n = 0; n < 4; n++)
            #pragma unroll
            for (int j = 0; j < 4; j++) acc[m][n][j] = 0.f;

    const uint4* pk4 = reinterpret_cast<const uint4*>(packed); // row stride 1024
    const uint32_t c1032b = 0x64086408u;                       // half2(1032,1032)
    const __half2 c1032 = *reinterpret_cast<const __half2*>(&c1032b);

    // ---- stage the scale table once: [NCH][TILE_N], float4-vectorized -----
    // thread i loads 4 consecutive chunks of one row: idx = row*NCH + ch4*4
    #pragma unroll
    for (int i = 0; i < (NCH * TILE_N) / (NTHREADS * 4); i++) {
        int v   = tid + i * NTHREADS;            // 0..255 (2 iters x 256 = 512? no: 1024/4=256)
        int row = v >> 1;                        // 0..127
        int c4  = v & 1;                         // which float4 of the row
        float4 f = *reinterpret_cast<const float4*>(
            scales + (size_t)(n0 + row) * 64 + kg * NCH + c4 * 4);
        // store transposed into [ch][row] layout used by dequant
        sScale[(c4 * 4 + 0) * TILE_N + row] = f.x;
        sScale[(c4 * 4 + 1) * TILE_N + row] = f.y;
        sScale[(c4 * 4 + 2) * TILE_N + row] = f.z;
        sScale[(c4 * 4 + 3) * TILE_N + row] = f.w;
    }

    // ---- packed-W register prefetch (one k64 sub = 1024 uint4 = 4/thread) -
    uint4 pv[4];
    auto prefetch = [&](int ks) {
        #pragma unroll
        for (int j = 0; j < 4; j++) {
            int u = tid + (j << 8);                  // 0..1023
            int row = u >> 3, kv = u & 7;
            pv[j] = pk4[(size_t)(n0 + row) * 1024 + ks * 8 + kv];
        }
    };

    // ---- x tile cp.async (512 x 16B units = 2/thread), L1-cached ----------
    auto stage_x = [&](int ks, int s) {
        const uint32_t xb = sb + s * STAGE_BYTES + X_OFF;
        #pragma unroll
        for (int j = 0; j < 2; j++) {
            int u = tid + (j << 8);                  // 0..511
            int b = u >> 3, kv = u & 7;
            cp_async16_ca(xb + b * RS + kv * 16,
                          &g_xh[(size_t)b * IN_K + ks * 64 + kv * 8]);
        }
        cp_commit();
    };

    // dequant pv (subchunk sub) -> W buffer s (4 x STS.128 / thread)
    auto dequant_sts = [&](int s, int sub) {
        const uint32_t stage = sb + s * STAGE_BYTES;
        const int lch = sub >> 1;                    // k128 scale chunk
        #pragma unroll
        for (int j = 0; j < 4; j++) {
            int u = tid + (j << 8);
            int row = u >> 3, kv = u & 7;
            __half2 s2 = __float2half2_rn(sScale[lch * TILE_N + row]);
            uint32_t w[4] = { pv[j].x, pv[j].y, pv[j].z, pv[j].w };
            uint32_t o[4];
            #pragma unroll
            for (int q = 0; q < 4; q++) {
                uint32_t t = ((w[q] * 0x1001u) & 0x000F000Fu) | 0x64006400u;
                __half2 hv = __hmul2(__hsub2(*reinterpret_cast<__half2*>(&t), c1032), s2);
                o[q] = *reinterpret_cast<uint32_t*>(&hv);
            }
            asm volatile("st.shared.v4.b32 [%0], {%1,%2,%3,%4};"
                         :: "r"(stage + row * RS + kv * 16),
                            "r"(o[0]), "r"(o[1]), "r"(o[2]), "r"(o[3]) : "memory");
        }
    };

    // ---- prologue ---------------------------------------------------------
    prefetch(ks0);           // pv = packed[sub 0]
    stage_x(ks0, 0);         // x[0] in flight
    __syncthreads();         // sScale visible to all
    dequant_sts(0, 0);       // W[0] STS -> stage 0
    prefetch(ks0 + 1);       // pv = packed[sub 1]

    // Invariant at iteration entry (sub, s = sub&1):
    //   x[sub] cp.async group pending; W[sub] STS issued into stage s;
    //   pv = packed[sub+1].
    for (int sub = 0; sub < NSUB; sub++) {
        const int s = sub & 1;

        asm volatile("cp.async.wait_group 0;" ::: "memory");  // x[sub] landed
        __syncthreads();     // W[sub]/x[sub] visible; stage s^1 free

        if (sub + 1 < NSUB) {
            stage_x(ks0 + sub + 1, s ^ 1);       // x[sub+1] in flight
            dequant_sts(s ^ 1, sub + 1);         // W[sub+1] STS (other buffer)
            if (sub + 2 < NSUB) prefetch(ks0 + sub + 2);  // LDGs overlap MMA
        }

        // ---- MMA(sub): 4 k16 tiles, warp tile 32(m) x 32(n), stage s ------
        const uint32_t wbase = sb + s * STAGE_BYTES;
        const uint32_t xbase = wbase + X_OFF;
        #pragma unroll
        for (int kt = 0; kt < 4; kt++) {
            uint32_t b[4][2];             // [nt][b0,b1]
            #pragma unroll
            for (int np = 0; np < 2; np++) {
                int br = ng * 32 + np * 16 + ((lane >> 4) & 1) * 8 + (lane & 7);
                int bc = kt * 16 + ((lane >> 3) & 1) * 8;
                ldsm_x4(b[np*2][0], b[np*2][1], b[np*2+1][0], b[np*2+1][1],
                        wbase + (uint32_t)(br * RS + bc * 2));
            }
            #pragma unroll
            for (int mt = 0; mt < 2; mt++) {
                uint32_t a0, a1, a2, a3;
                int ar = mh * 32 + mt * 16 + (lane & 15);
                int ac = kt * 16 + (lane >> 4) * 8;
                ldsm_x4(a0, a1, a2, a3, xbase + (uint32_t)(ar * RS + ac * 2));
                #pragma unroll
                for (int nt = 0; nt < 4; nt++)
                    mma_16816(acc[mt][nt], a0, a1, a2, a3, b[nt][0], b[nt][1]);
            }
        }
    }

    // ---- epilogue: vectorized float2 atomics (k-split merge) --------------
    #pragma unroll
    for (int mt = 0; mt < 2; mt++) {
        #pragma unroll
        for (int nt = 0; nt < 4; nt++) {
            int m = mh * 32 + mt * 16 + (lane >> 2);
            int n = n0 + ng * 32 + nt * 8 + (lane & 3) * 2;
            atomicAdd(reinterpret_cast<float2*>(&out[(size_t)m * OUT_N + n]),
                      make_float2(acc[mt][nt][0], acc[mt][nt][1]));
            atomicAdd(reinterpret_cast<float2*>(&out[(size_t)(m + 8) * OUT_N + n]),
                      make_float2(acc[mt][nt][2], acc[mt][nt][3]));
        }
    }
}

// ---------------------------------------------------------------------------
extern "C" void kernel_launch(void* const* d_in, const int* in_sizes, int n_in,
                              void* d_out, int out_size) {
    const float* x      = (const float*)d_in[0];
    const int*   packed = (const int*)d_in[1];
    const float* scales = (const float*)d_in[2];
    float*       out    = (float*)d_out;

    cudaFuncSetAttribute(dq_gemm_kernel,
                         cudaFuncAttributeMaxDynamicSharedMemorySize, SMEM_TOTAL);

    prep_kernel<<<128, 256>>>(x, out);
    dq_gemm_kernel<<<NGRPS * KSPLIT, NTHREADS, SMEM_TOTAL>>>(packed, scales, out);
}